// round 4
// baseline (speedup 1.0000x reference)
#include <cuda_runtime.h>
#include <cuda_bf16.h>
#include <cstdint>

// Problem dims
#define BATCH 1024
#define TSTEPS 200
#define DDIM 128

#define NBLK 128          // 8 M-tiles x 16 cell-tiles, 1 CTA/SM
#define THREADS 256
#define MT 128            // batch rows per CTA
#define CT_CELLS 8        // cells per CTA -> 32 gate-columns

// SMEM layout (bytes): swizzled bf16 tiles, 512B per logical row
#define SM_AHI 0
#define SM_ALO (SM_AHI + 128*512)
#define SM_BHI (SM_ALO + 128*512)
#define SM_BLO (SM_BHI + 32*512)
#define SMEM_BYTES (SM_BLO + 32*512)   // 163840

// Persistent state + barrier (device globals: no allocation allowed)
__device__ float g_h1[2][BATCH*DDIM];
__device__ float g_h2[2][BATCH*DDIM];
__device__ unsigned g_bar_count;
__device__ unsigned g_bar_gen;

// ---------------- helpers ----------------
__device__ __forceinline__ uint32_t smem_u32(const void* p){
    uint32_t a;
    asm("{ .reg .u64 t; cvta.to.shared.u64 t, %1; cvt.u32.u64 %0, t; }" : "=r"(a) : "l"(p));
    return a;
}
__device__ __forceinline__ void ldsm4(uint32_t& r0, uint32_t& r1, uint32_t& r2, uint32_t& r3, uint32_t addr){
    asm volatile("ldmatrix.sync.aligned.m8n8.x4.shared.b16 {%0,%1,%2,%3}, [%4];"
                 : "=r"(r0), "=r"(r1), "=r"(r2), "=r"(r3) : "r"(addr));
}
__device__ __forceinline__ void hmma(float* c, const uint32_t* a, uint32_t b0, uint32_t b1){
    asm volatile("mma.sync.aligned.m16n8k16.row.col.f32.bf16.bf16.f32 "
                 "{%0,%1,%2,%3}, {%4,%5,%6,%7}, {%8,%9}, {%0,%1,%2,%3};"
                 : "+f"(c[0]), "+f"(c[1]), "+f"(c[2]), "+f"(c[3])
                 : "r"(a[0]), "r"(a[1]), "r"(a[2]), "r"(a[3]), "r"(b0), "r"(b1));
}
__device__ __forceinline__ float fsig(float x){ return __fdividef(1.f, 1.f + __expf(-x)); }
__device__ __forceinline__ float ftanh_(float x){
    x = fminf(15.f, fmaxf(-15.f, x));
    float e = __expf(2.f * x);
    return __fdividef(e - 1.f, e + 1.f);
}
// split fp32 quad -> packed bf16x2 hi/lo pairs
__device__ __forceinline__ void split4(float4 v, uint2& hi, uint2& lo){
    __nv_bfloat16 hx = __float2bfloat16(v.x), hy = __float2bfloat16(v.y),
                  hz = __float2bfloat16(v.z), hw = __float2bfloat16(v.w);
    __nv_bfloat16 lx = __float2bfloat16(v.x - __bfloat162float(hx));
    __nv_bfloat16 ly = __float2bfloat16(v.y - __bfloat162float(hy));
    __nv_bfloat16 lz = __float2bfloat16(v.z - __bfloat162float(hz));
    __nv_bfloat16 lw = __float2bfloat16(v.w - __bfloat162float(hw));
    __nv_bfloat162 h01; h01.x = hx; h01.y = hy;
    __nv_bfloat162 h23; h23.x = hz; h23.y = hw;
    __nv_bfloat162 l01; l01.x = lx; l01.y = ly;
    __nv_bfloat162 l23; l23.x = lz; l23.y = lw;
    hi.x = *reinterpret_cast<uint32_t*>(&h01); hi.y = *reinterpret_cast<uint32_t*>(&h23);
    lo.x = *reinterpret_cast<uint32_t*>(&l01); lo.y = *reinterpret_cast<uint32_t*>(&l23);
}
__device__ __forceinline__ void grid_barrier(){
    __syncthreads();
    if (threadIdx.x == 0){
        __threadfence();
        unsigned my = *(volatile unsigned*)&g_bar_gen;
        unsigned old = atomicAdd(&g_bar_count, 1);
        if (old == NBLK - 1){
            g_bar_count = 0;
            __threadfence();
            atomicAdd(&g_bar_gen, 1);
        } else {
            while (*(volatile unsigned*)&g_bar_gen == my) { }
        }
        __threadfence();
    }
    __syncthreads();
}

extern __shared__ char smem[];

__global__ void __launch_bounds__(THREADS, 1)
lstm_hmma_kernel(const float* __restrict__ x,
                 const float* __restrict__ W,
                 const float* __restrict__ U,
                 const float* __restrict__ bias,
                 float* __restrict__ out)
{
    const uint32_t sbase = smem_u32(smem);
    const int tid = threadIdx.x;
    const int wid = tid >> 5, lane = tid & 31;
    const int mt = blockIdx.x >> 4;       // 0..7
    const int ct = blockIdx.x & 15;       // 0..15
    const int m0 = mt * MT;
    const int cell0 = ct * CT_CELLS;

    // ---- build B hi/lo in SMEM once: n = gate*8 + cell, [32 n][256 k], swizzled
    #pragma unroll
    for (int i = 0; i < 8; ++i){
        int tsk = tid + i * THREADS;                 // 0..2047 (32 n * 64 kq)
        int n = tsk >> 6, kq = tsk & 63, k = kq * 4;
        int gate = n >> 3, cell = n & 7;
        int col = gate * 128 + cell0 + cell;
        float4 v;
        float* vv = reinterpret_cast<float*>(&v);
        #pragma unroll
        for (int j = 0; j < 4; ++j){
            int kk = k + j;
            vv[j] = (kk < 128) ? W[kk * 512 + col] : U[(kk - 128) * 512 + col];
        }
        uint2 hi, lo; split4(v, hi, lo);
        uint32_t so = n * 512 + ((((kq >> 1) ^ (n & 7)) << 4)) + ((kq & 1) << 3);
        *reinterpret_cast<uint2*>(smem + SM_BHI + so) = hi;
        *reinterpret_cast<uint2*>(smem + SM_BLO + so) = lo;
    }

    // ---- zero recurrent state for this M-tile (redundant across ct; fine)
    for (int i = tid; i < MT * DDIM; i += THREADS){
        int r = i >> 7, c = i & 127;
        g_h1[0][(m0 + r) * DDIM + c] = 0.f;
        g_h2[0][(m0 + r) * DDIM + c] = 0.f;
    }
    grid_barrier();

    // ---- epilogue/fragment coordinates
    const int frow = (lane >> 2);                 // fragment row 0..3
    const int c0 = (lane & 3) * 2;                // cell pair within the 8 cells
    const int row_g = m0 + wid * 16 + frow;       // global row (j=0,1); +8 for j=2,3

    // bias per (gate, cellpair), folded into accumulator init
    float bia[4][2];
    #pragma unroll
    for (int g = 0; g < 4; ++g){
        bia[g][0] = bias[g * 128 + cell0 + c0];
        bia[g][1] = bias[g * 128 + cell0 + c0 + 1];
    }

    // ldmatrix lane address components
    const int a_row = wid * 16 + (lane & 15);
    const uint32_t a_base = a_row * 512;
    const uint32_t a_xor = (a_row & 7) << 4;
    const uint32_t a_lk = (lane >> 4) << 4;           // +16B for k+8 half
    const int b_row01 = (lane & 7) + ((lane >> 4) << 3);       // gates 0/1 block
    const int b_row23 = 16 + b_row01;                          // gates 2/3 block
    const uint32_t b01_base = b_row01 * 512, b01_xor = (b_row01 & 7) << 4;
    const uint32_t b23_base = b_row23 * 512, b23_xor = (b_row23 & 7) << 4;
    const uint32_t b_lk = ((lane >> 3) & 1) << 4;

    float c1[4], c2[4], h1n[4];
    #pragma unroll
    for (int j = 0; j < 4; ++j){ c1[j] = 0.f; c2[j] = 0.f; }

    for (int t = 0; t < TSTEPS; ++t){
        const int p = t & 1, pn = p ^ 1;

        #pragma unroll 1
        for (int phase = 0; phase < 2; ++phase){
            // ===== A fill: [x_t | h1(p)]  or  [h1(pn) | h2(p)] =====
            __syncthreads();   // prior phase's MMAs done reading sA
            #pragma unroll 4
            for (int i = 0; i < 32; ++i){
                int tsk = tid + i * THREADS;              // 0..8191 (128 rows * 64 kq)
                int row = tsk >> 6, kq = tsk & 63, k = kq * 4;
                float4 v;
                if (phase == 0){
                    if (k < 128) v = *reinterpret_cast<const float4*>(&x[((m0 + row) * TSTEPS + t) * DDIM + k]);
                    else         v = __ldcg(reinterpret_cast<const float4*>(&g_h1[p][(m0 + row) * DDIM + (k - 128)]));
                } else {
                    if (k < 128) v = __ldcg(reinterpret_cast<const float4*>(&g_h1[pn][(m0 + row) * DDIM + k]));
                    else         v = __ldcg(reinterpret_cast<const float4*>(&g_h2[p][(m0 + row) * DDIM + (k - 128)]));
                }
                uint2 hi, lo; split4(v, hi, lo);
                uint32_t so = row * 512 + ((((kq >> 1) ^ (row & 7)) << 4)) + ((kq & 1) << 3);
                *reinterpret_cast<uint2*>(smem + SM_AHI + so) = hi;
                *reinterpret_cast<uint2*>(smem + SM_ALO + so) = lo;
            }
            __syncthreads();

            // ===== 3xBF16 GEMM: acc = bias + Ahi*Bhi + Ahi*Blo + Alo*Bhi =====
            float acc[4][4];
            #pragma unroll
            for (int g = 0; g < 4; ++g){
                acc[g][0] = bia[g][0]; acc[g][1] = bia[g][1];
                acc[g][2] = bia[g][0]; acc[g][3] = bia[g][1];
            }
            #pragma unroll 4
            for (int ks = 0; ks < 16; ++ks){
                uint32_t kb = ks * 32;
                uint32_t ahi[4], alo[4], bh[8], bl[8];
                uint32_t ao = (kb + a_lk) ^ a_xor;
                ldsm4(ahi[0], ahi[1], ahi[2], ahi[3], sbase + SM_AHI + a_base + ao);
                ldsm4(alo[0], alo[1], alo[2], alo[3], sbase + SM_ALO + a_base + ao);
                uint32_t bo01 = (kb + b_lk) ^ b01_xor;
                uint32_t bo23 = (kb + b_lk) ^ b23_xor;
                ldsm4(bh[0], bh[1], bh[2], bh[3], sbase + SM_BHI + b01_base + bo01);
                ldsm4(bh[4], bh[5], bh[6], bh[7], sbase + SM_BHI + b23_base + bo23);
                ldsm4(bl[0], bl[1], bl[2], bl[3], sbase + SM_BLO + b01_base + bo01);
                ldsm4(bl[4], bl[5], bl[6], bl[7], sbase + SM_BLO + b23_base + bo23);
                #pragma unroll
                for (int g = 0; g < 4; ++g){
                    hmma(acc[g], ahi, bh[g * 2], bh[g * 2 + 1]);
                    hmma(acc[g], ahi, bl[g * 2], bl[g * 2 + 1]);
                    hmma(acc[g], alo, bh[g * 2], bh[g * 2 + 1]);
                }
            }

            // ===== LSTM epilogue (thread-local: 2 rows x 2 cells) =====
            if (phase == 0){
                float2 st0, st1;
                #pragma unroll
                for (int j = 0; j < 4; ++j){
                    float cn = fsig(acc[1][j]) * c1[j] + fsig(acc[0][j]) * ftanh_(acc[2][j]);
                    c1[j] = cn;
                    h1n[j] = fsig(acc[3][j]) * ftanh_(cn);
                }
                st0.x = h1n[0]; st0.y = h1n[1];
                st1.x = h1n[2]; st1.y = h1n[3];
                *reinterpret_cast<float2*>(&g_h1[pn][row_g * DDIM + cell0 + c0]) = st0;
                *reinterpret_cast<float2*>(&g_h1[pn][(row_g + 8) * DDIM + cell0 + c0]) = st1;
                grid_barrier();     // h1(t+1) globally visible
            } else {
                float hv[4];
                #pragma unroll
                for (int j = 0; j < 4; ++j){
                    float cn = fsig(acc[1][j]) * c2[j] + fsig(acc[0][j]) * ftanh_(acc[2][j]);
                    c2[j] = cn;
                    hv[j] = fsig(acc[3][j]) * ftanh_(cn) + h1n[j];   // residual
                }
                float2 st0, st1;
                st0.x = hv[0]; st0.y = hv[1];
                st1.x = hv[2]; st1.y = hv[3];
                *reinterpret_cast<float2*>(&g_h2[pn][row_g * DDIM + cell0 + c0]) = st0;
                *reinterpret_cast<float2*>(&g_h2[pn][(row_g + 8) * DDIM + cell0 + c0]) = st1;
                *reinterpret_cast<float2*>(&out[(row_g * TSTEPS + t) * DDIM + cell0 + c0]) = st0;
                *reinterpret_cast<float2*>(&out[((row_g + 8) * TSTEPS + t) * DDIM + cell0 + c0]) = st1;
                // no barrier: hazards separated by next step's barrier (double buffering)
            }
        }
    }
}

extern "C" void kernel_launch(void* const* d_in, const int* in_sizes, int n_in,
                              void* d_out, int out_size)
{
    const float* x    = (const float*)d_in[0];
    const float* W    = (const float*)d_in[1];
    const float* U    = (const float*)d_in[2];
    const float* bias = (const float*)d_in[3];
    // d_in[4] = seq_len: reference ignores it
    float* out = (float*)d_out;

    cudaFuncSetAttribute(lstm_hmma_kernel,
                         cudaFuncAttributeMaxDynamicSharedMemorySize, SMEM_BYTES);
    lstm_hmma_kernel<<<NBLK, THREADS, SMEM_BYTES>>>(x, W, U, bias, out);
}

// round 5
// speedup vs baseline: 4.0385x; 4.0385x over previous
#include <cuda_runtime.h>
#include <cuda_bf16.h>
#include <cstdint>

// Problem dims
#define BATCH 1024
#define TSTEPS 200
#define DDIM 128

#define NBLK 128          // 16 m-groups x 8 cell-CTAs
#define THREADS 256
#define MT 64             // batch rows per CTA
#define NGRP 16
#define GRP_CTAS 8
#define CT_CELLS 16       // cells per CTA -> 64 gate-columns

// SMEM (bytes): A double-buffered hi/lo [64 rows x 512B], B hi/lo [64 n x 512B]
#define SM_A0HI 0
#define SM_A0LO 32768
#define SM_A1HI 65536
#define SM_A1LO 98304
#define SM_BHI  131072
#define SM_BLO  163840
#define SMEM_BYTES 196608

// Persistent globals (no allocation allowed)
__device__ __nv_bfloat16 gx_hi[BATCH*TSTEPS*DDIM];
__device__ __nv_bfloat16 gx_lo[BATCH*TSTEPS*DDIM];
__device__ __nv_bfloat16 gh1_hi[2][BATCH*DDIM];
__device__ __nv_bfloat16 gh1_lo[2][BATCH*DDIM];
__device__ __nv_bfloat16 gh2_hi[2][BATCH*DDIM];
__device__ __nv_bfloat16 gh2_lo[2][BATCH*DDIM];
__device__ unsigned g_bar_count[NGRP];
__device__ unsigned g_bar_gen[NGRP];

// ---------------- helpers ----------------
__device__ __forceinline__ uint32_t smem_u32(const void* p){
    uint32_t a;
    asm("{ .reg .u64 t; cvta.to.shared.u64 t, %1; cvt.u32.u64 %0, t; }" : "=r"(a) : "l"(p));
    return a;
}
__device__ __forceinline__ void cpa16(uint32_t dst, const void* src){
    asm volatile("cp.async.cg.shared.global [%0], [%1], 16;" :: "r"(dst), "l"(src));
}
__device__ __forceinline__ void cp_commit(){ asm volatile("cp.async.commit_group;" ::: "memory"); }
template<int N> __device__ __forceinline__ void cp_wait(){ asm volatile("cp.async.wait_group %0;" :: "n"(N) : "memory"); }

__device__ __forceinline__ void ldsm4(uint32_t& r0, uint32_t& r1, uint32_t& r2, uint32_t& r3, uint32_t addr){
    asm volatile("ldmatrix.sync.aligned.m8n8.x4.shared.b16 {%0,%1,%2,%3}, [%4];"
                 : "=r"(r0), "=r"(r1), "=r"(r2), "=r"(r3) : "r"(addr));
}
__device__ __forceinline__ void hmma(float* c, const uint32_t* a, uint32_t b0, uint32_t b1){
    asm volatile("mma.sync.aligned.m16n8k16.row.col.f32.bf16.bf16.f32 "
                 "{%0,%1,%2,%3}, {%4,%5,%6,%7}, {%8,%9}, {%0,%1,%2,%3};"
                 : "+f"(c[0]), "+f"(c[1]), "+f"(c[2]), "+f"(c[3])
                 : "r"(a[0]), "r"(a[1]), "r"(a[2]), "r"(a[3]), "r"(b0), "r"(b1));
}
__device__ __forceinline__ float fsig(float x){ return __fdividef(1.f, 1.f + __expf(-x)); }
__device__ __forceinline__ float ftanh_(float x){
    x = fminf(15.f, fmaxf(-15.f, x));
    float e = __expf(2.f * x);
    return __fdividef(e - 1.f, e + 1.f);
}
__device__ __forceinline__ void split1(float v, __nv_bfloat16& hi, __nv_bfloat16& lo){
    hi = __float2bfloat16(v);
    lo = __float2bfloat16(v - __bfloat162float(hi));
}
__device__ __forceinline__ void split4(float4 v, uint2& hi, uint2& lo){
    __nv_bfloat16 hx, hy, hz, hw, lx, ly, lz, lw;
    split1(v.x, hx, lx); split1(v.y, hy, ly); split1(v.z, hz, lz); split1(v.w, hw, lw);
    __nv_bfloat162 h01; h01.x = hx; h01.y = hy;
    __nv_bfloat162 h23; h23.x = hz; h23.y = hw;
    __nv_bfloat162 l01; l01.x = lx; l01.y = ly;
    __nv_bfloat162 l23; l23.x = lz; l23.y = lw;
    hi.x = *reinterpret_cast<uint32_t*>(&h01); hi.y = *reinterpret_cast<uint32_t*>(&h23);
    lo.x = *reinterpret_cast<uint32_t*>(&l01); lo.y = *reinterpret_cast<uint32_t*>(&l23);
}

__device__ __forceinline__ void group_barrier(int grp){
    __syncthreads();
    if (threadIdx.x == 0){
        __threadfence();
        unsigned my = *(volatile unsigned*)&g_bar_gen[grp];
        unsigned old = atomicAdd(&g_bar_count[grp], 1);
        if (old == GRP_CTAS - 1){
            g_bar_count[grp] = 0;
            __threadfence();
            atomicAdd(&g_bar_gen[grp], 1);
        } else {
            while (*(volatile unsigned*)&g_bar_gen[grp] == my) { }
        }
        __threadfence();
    }
    __syncthreads();
}

// fill one K-half (hi+lo) of an A buffer via cp.async (2048 x 16B)
__device__ __forceinline__ void fill_half(uint32_t sb_hi, uint32_t sb_lo,
                                          const __nv_bfloat16* __restrict__ src_hi,
                                          const __nv_bfloat16* __restrict__ src_lo,
                                          size_t row_stride, int half, int tid){
    #pragma unroll
    for (int i = 0; i < 8; ++i){
        int idx = tid + i * THREADS;      // 0..2047
        int sel = idx >> 10;              // 0 = hi, 1 = lo
        int r = (idx >> 4) & 63;
        int u = idx & 15;
        const __nv_bfloat16* s = (sel ? src_lo : src_hi) + (size_t)r * row_stride + u * 8;
        uint32_t U = (uint32_t)((half << 4) | u);
        uint32_t dst = (sel ? sb_lo : sb_hi) + r * 512 + ((U ^ (uint32_t)(r & 7)) << 4);
        cpa16(dst, s);
    }
}

// -------- pre-kernel: split x into bf16 hi/lo --------
__global__ void __launch_bounds__(256)
split_x_kernel(const float* __restrict__ x)
{
    int i = blockIdx.x * 256 + threadIdx.x;   // float4 index
    float4 v = reinterpret_cast<const float4*>(x)[i];
    uint2 hi, lo; split4(v, hi, lo);
    reinterpret_cast<uint2*>(gx_hi)[i] = hi;
    reinterpret_cast<uint2*>(gx_lo)[i] = lo;
}

extern __shared__ char smem[];

// -------- main persistent kernel --------
__global__ void __launch_bounds__(THREADS, 1)
lstm_hmma2_kernel(const float* __restrict__ W,
                  const float* __restrict__ U,
                  const float* __restrict__ bias,
                  float* __restrict__ out)
{
    const uint32_t sbase = smem_u32(smem);
    const int tid = threadIdx.x;
    const int wid = tid >> 5, lane = tid & 31;
    const int mt = blockIdx.x >> 3;       // 0..15 (m-group)
    const int ct = blockIdx.x & 7;        // 0..7
    const int m0 = mt * MT;
    const int cell0 = ct * CT_CELLS;

    // ---- build B hi/lo once: n = gate*16 + cell, [64 n][256 k] swizzled
    #pragma unroll
    for (int i = 0; i < 16; ++i){
        int tsk = tid + i * THREADS;              // 0..4095 (64 n * 64 kq)
        int n = tsk >> 6, kq = tsk & 63, k = kq * 4;
        int gate = n >> 4, cell = n & 15;
        int col = gate * 128 + cell0 + cell;
        float4 v;
        float* vv = reinterpret_cast<float*>(&v);
        #pragma unroll
        for (int j = 0; j < 4; ++j){
            int kk = k + j;
            vv[j] = (kk < 128) ? W[kk * 512 + col] : U[(kk - 128) * 512 + col];
        }
        uint2 hi, lo; split4(v, hi, lo);
        uint32_t so = n * 512 + ((((kq >> 1) ^ (n & 7)) << 4)) + ((kq & 1) << 3);
        *reinterpret_cast<uint2*>(smem + SM_BHI + so) = hi;
        *reinterpret_cast<uint2*>(smem + SM_BLO + so) = lo;
    }

    // ---- zero initial split state (slot 0) for this m-tile
    for (int i = tid; i < MT * DDIM / 2; i += THREADS){
        reinterpret_cast<uint32_t*>(&gh1_hi[0][m0 * DDIM])[i] = 0u;
        reinterpret_cast<uint32_t*>(&gh1_lo[0][m0 * DDIM])[i] = 0u;
        reinterpret_cast<uint32_t*>(&gh2_hi[0][m0 * DDIM])[i] = 0u;
        reinterpret_cast<uint32_t*>(&gh2_lo[0][m0 * DDIM])[i] = 0u;
    }
    group_barrier(mt);

    // ---- prefetch bufA for t=0: half0 = x(0), half1 = h1(0)
    fill_half(sbase + SM_A0HI, sbase + SM_A0LO,
              gx_hi + (size_t)m0 * TSTEPS * DDIM, gx_lo + (size_t)m0 * TSTEPS * DDIM,
              (size_t)TSTEPS * DDIM, 0, tid);
    fill_half(sbase + SM_A0HI, sbase + SM_A0LO,
              &gh1_hi[0][m0 * DDIM], &gh1_lo[0][m0 * DDIM], DDIM, 1, tid);
    cp_commit();

    // ---- per-warp fragment coordinates
    const int mblk = wid >> 1;                   // 0..3 : 16-row block
    const int ch = wid & 1;                      // cell half (8 cells)
    const int frow = lane >> 2;                  // 0..7
    const int c0 = (lane & 3) * 2;               // cell pair
    const int row_g = m0 + mblk * 16 + frow;     // rows row_g, row_g+8
    const int cellg = cell0 + ch * 8 + c0;       // cells cellg, cellg+1

    const int a_row = mblk * 16 + (lane & 15);
    const uint32_t a_base = a_row * 512;
    const uint32_t a_xor = (a_row & 7) << 4;
    const uint32_t a_lk = (lane >> 4) << 4;
    const int b_row01 = ch * 8 + (lane & 7) + ((lane >> 4) << 4);
    const int b_row23 = 32 + b_row01;
    const uint32_t b01_base = b_row01 * 512, b01_xor = (b_row01 & 7) << 4;
    const uint32_t b23_base = b_row23 * 512, b23_xor = (b_row23 & 7) << 4;
    const uint32_t b_lk = ((lane >> 3) & 1) << 4;

    float bia[4][2];
    #pragma unroll
    for (int g = 0; g < 4; ++g){
        bia[g][0] = bias[g * 128 + cellg];
        bia[g][1] = bias[g * 128 + cellg + 1];
    }

    float c1[4], c2[4], h1n[4];
    #pragma unroll
    for (int j = 0; j < 4; ++j){ c1[j] = 0.f; c2[j] = 0.f; }

    float acc[4][4];

    // GEMM over one A buffer (by hi/lo smem byte offsets)
    auto run_mma = [&](uint32_t off_hi, uint32_t off_lo){
        #pragma unroll
        for (int g = 0; g < 4; ++g){
            acc[g][0] = bia[g][0]; acc[g][1] = bia[g][1];
            acc[g][2] = bia[g][0]; acc[g][3] = bia[g][1];
        }
        #pragma unroll 4
        for (int ks = 0; ks < 16; ++ks){
            uint32_t kb = ks * 32;
            uint32_t ahi[4], alo[4], bh[8], bl[8];
            uint32_t ao = (kb + a_lk) ^ a_xor;
            ldsm4(ahi[0], ahi[1], ahi[2], ahi[3], sbase + off_hi + a_base + ao);
            ldsm4(alo[0], alo[1], alo[2], alo[3], sbase + off_lo + a_base + ao);
            uint32_t bo01 = (kb + b_lk) ^ b01_xor;
            uint32_t bo23 = (kb + b_lk) ^ b23_xor;
            ldsm4(bh[0], bh[1], bh[2], bh[3], sbase + SM_BHI + b01_base + bo01);
            ldsm4(bh[4], bh[5], bh[6], bh[7], sbase + SM_BHI + b23_base + bo23);
            ldsm4(bl[0], bl[1], bl[2], bl[3], sbase + SM_BLO + b01_base + bo01);
            ldsm4(bl[4], bl[5], bl[6], bl[7], sbase + SM_BLO + b23_base + bo23);
            #pragma unroll
            for (int g = 0; g < 4; ++g){
                hmma(acc[g], ahi, bh[g * 2], bh[g * 2 + 1]);
                hmma(acc[g], ahi, bl[g * 2], bl[g * 2 + 1]);
                hmma(acc[g], alo, bh[g * 2], bh[g * 2 + 1]);
            }
        }
    };

    for (int t = 0; t < TSTEPS; ++t){
        const int slot = t & 1, nslot = slot ^ 1;

        // ===== Phase 0: z1 = [x_t | h1(t)] (bufA, prefetched) =====
        cp_wait<0>();
        __syncthreads();
        run_mma(SM_A0HI, SM_A0LO);

        #pragma unroll
        for (int j = 0; j < 4; ++j){
            float cn = fsig(acc[1][j]) * c1[j] + fsig(acc[0][j]) * ftanh_(acc[2][j]);
            c1[j] = cn;
            h1n[j] = fsig(acc[3][j]) * ftanh_(cn);
        }
        #pragma unroll
        for (int half = 0; half < 2; ++half){
            int r = row_g + half * 8;
            __nv_bfloat162 hh, ll;
            split1(h1n[half * 2 + 0], hh.x, ll.x);
            split1(h1n[half * 2 + 1], hh.y, ll.y);
            *reinterpret_cast<__nv_bfloat162*>(&gh1_hi[nslot][r * DDIM + cellg]) = hh;
            *reinterpret_cast<__nv_bfloat162*>(&gh1_lo[nslot][r * DDIM + cellg]) = ll;
        }

        group_barrier(mt);   // h1(t+1) globally visible; also guards bufA/bufB reuse

        // prefetch bufB: half0 = h1(t+1), half1 = h2(t)
        fill_half(sbase + SM_A1HI, sbase + SM_A1LO,
                  &gh1_hi[nslot][m0 * DDIM], &gh1_lo[nslot][m0 * DDIM], DDIM, 0, tid);
        fill_half(sbase + SM_A1HI, sbase + SM_A1LO,
                  &gh2_hi[slot][m0 * DDIM], &gh2_lo[slot][m0 * DDIM], DDIM, 1, tid);
        cp_commit();
        // prefetch bufA for next step: half0 = x(t+1), half1 = h1(t+1)
        if (t < TSTEPS - 1){
            fill_half(sbase + SM_A0HI, sbase + SM_A0LO,
                      gx_hi + ((size_t)m0 * TSTEPS + (t + 1)) * DDIM,
                      gx_lo + ((size_t)m0 * TSTEPS + (t + 1)) * DDIM,
                      (size_t)TSTEPS * DDIM, 0, tid);
            fill_half(sbase + SM_A0HI, sbase + SM_A0LO,
                      &gh1_hi[nslot][m0 * DDIM], &gh1_lo[nslot][m0 * DDIM], DDIM, 1, tid);
            cp_commit();
            cp_wait<1>();    // bufB ready, bufA still in flight
        } else {
            cp_wait<0>();
        }
        __syncthreads();

        // ===== Phase 1: z2 = [h1(t+1) | h2(t)] (bufB) =====
        run_mma(SM_A1HI, SM_A1LO);

        #pragma unroll
        for (int j = 0; j < 4; ++j){
            float cn = fsig(acc[1][j]) * c2[j] + fsig(acc[0][j]) * ftanh_(acc[2][j]);
            c2[j] = cn;
            acc[0][j] = fsig(acc[3][j]) * ftanh_(cn) + h1n[j];   // hv, reuse acc
        }
        #pragma unroll
        for (int half = 0; half < 2; ++half){
            int r = row_g + half * 8;
            __nv_bfloat162 hh, ll;
            split1(acc[0][half * 2 + 0], hh.x, ll.x);
            split1(acc[0][half * 2 + 1], hh.y, ll.y);
            *reinterpret_cast<__nv_bfloat162*>(&gh2_hi[nslot][r * DDIM + cellg]) = hh;
            *reinterpret_cast<__nv_bfloat162*>(&gh2_lo[nslot][r * DDIM + cellg]) = ll;
            float2 ov; ov.x = acc[0][half * 2 + 0]; ov.y = acc[0][half * 2 + 1];
            *reinterpret_cast<float2*>(&out[((size_t)r * TSTEPS + t) * DDIM + cellg]) = ov;
        }
        // no CTA sync needed here: bufB is next written only after the next
        // step's group_barrier (which includes __syncthreads)
    }
}

extern "C" void kernel_launch(void* const* d_in, const int* in_sizes, int n_in,
                              void* d_out, int out_size)
{
    const float* x    = (const float*)d_in[0];
    const float* W    = (const float*)d_in[1];
    const float* U    = (const float*)d_in[2];
    const float* bias = (const float*)d_in[3];
    // d_in[4] = seq_len: reference ignores it
    float* out = (float*)d_out;

    split_x_kernel<<<(BATCH * TSTEPS * DDIM / 4) / 256, 256>>>(x);

    cudaFuncSetAttribute(lstm_hmma2_kernel,
                         cudaFuncAttributeMaxDynamicSharedMemorySize, SMEM_BYTES);
    lstm_hmma2_kernel<<<NBLK, THREADS, SMEM_BYTES>>>(W, U, bias, out);
}